// round 2
// baseline (speedup 1.0000x reference)
#include <cuda_runtime.h>
#include <math.h>

#define NN 8192
#define DD 128
#define WVW 300

__device__ unsigned g_fp_bits[NN];   // furthest-positive, float bits (all >= 0)
__device__ unsigned g_cn_bits[NN];   // closest-negative,  float bits (all >= 0)
__device__ float    g_semnorm[NN];
__device__ float    g_xnorm[NN];

// ---------------------------------------------------------------------------
__global__ void init_kernel() {
    int i = blockIdx.x * blockDim.x + threadIdx.x;
    if (i < NN) {
        g_fp_bits[i] = 0u;                // 0.0f
        g_cn_bits[i] = 0x7F7FFFFFu;       // FLT_MAX
    }
}

// ---------------------------------------------------------------------------
// sem[n][d] = alpha[n] * (sum_w wv[n][w] * W[d][w] + b[d]) + (1-alpha[n]) * x[n][d]
// Tile: 64 rows x 128 dims, K tiles of 50.  grid = 128 blocks, 256 threads.
__global__ __launch_bounds__(256) void sem_kernel(
    const float* __restrict__ wv, const float* __restrict__ Wm,
    const float* __restrict__ bias, const float* __restrict__ x,
    const float* __restrict__ alpha, float* __restrict__ sem)
{
    __shared__ float As[64 * 50];    // As[r][kk]
    __shared__ float Ws[50 * 128];   // Ws[kk][d]

    const int i0 = blockIdx.x * 64;
    const int t  = threadIdx.x;
    const int tx = t & 15;           // 16 col-groups of 8
    const int ty = t >> 4;           // 16 row-groups of 4

    float acc[4][8];
#pragma unroll
    for (int r = 0; r < 4; r++)
#pragma unroll
        for (int c = 0; c < 8; c++) acc[r][c] = 0.f;

    for (int k0 = 0; k0 < WVW; k0 += 50) {
        for (int e = t; e < 64 * 50; e += 256) {
            int r = e / 50, kk = e % 50;
            As[e] = wv[(i0 + r) * WVW + k0 + kk];
        }
        for (int e = t; e < 50 * 128; e += 256) {
            int d = e / 50, kk = e % 50;
            Ws[kk * 128 + d] = Wm[d * WVW + k0 + kk];
        }
        __syncthreads();
#pragma unroll 5
        for (int kk = 0; kk < 50; kk++) {
            float a[4], bb[8];
#pragma unroll
            for (int r = 0; r < 4; r++) a[r] = As[(ty * 4 + r) * 50 + kk];
#pragma unroll
            for (int c = 0; c < 8; c++) bb[c] = Ws[kk * 128 + tx * 8 + c];
#pragma unroll
            for (int r = 0; r < 4; r++)
#pragma unroll
                for (int c = 0; c < 8; c++) acc[r][c] = fmaf(a[r], bb[c], acc[r][c]);
        }
        __syncthreads();
    }

#pragma unroll
    for (int r = 0; r < 4; r++) {
        int gi = i0 + ty * 4 + r;
        float al = alpha[gi];
#pragma unroll
        for (int c = 0; c < 8; c++) {
            int gc = tx * 8 + c;
            float v = acc[r][c] + bias[gc];
            sem[gi * DD + gc] = al * v + (1.0f - al) * x[gi * DD + gc];
        }
    }
}

// ---------------------------------------------------------------------------
// One warp per row: squared L2 norm of x rows (wid < N) and sem rows (wid >= N).
__global__ void norms_kernel(const float* __restrict__ x, const float* __restrict__ sem) {
    int wid  = (blockIdx.x * blockDim.x + threadIdx.x) >> 5;
    int lane = threadIdx.x & 31;
    const float* row;
    if (wid < NN) row = x + (size_t)wid * DD;
    else          row = sem + (size_t)(wid - NN) * DD;
    float4 v = reinterpret_cast<const float4*>(row)[lane];
    float s = v.x * v.x + v.y * v.y + v.z * v.z + v.w * v.w;
#pragma unroll
    for (int o = 16; o > 0; o >>= 1) s += __shfl_xor_sync(0xFFFFFFFFu, s, o);
    if (lane == 0) {
        if (wid < NN) g_xnorm[wid] = s;
        else          g_semnorm[wid - NN] = s;
    }
}

// ---------------------------------------------------------------------------
// Fused pairwise-distance GEMM + batch-hard reduction.
// 128x128 C tile per block, K = 128 (4 k-tiles of 32), 256 threads, 8x8 regs.
#define KT 32
#define ASTRIDE 129   // padded: makes transposed STS conflict-free

__global__ __launch_bounds__(256) void dist_kernel(
    const float* __restrict__ sem, const float* __restrict__ x,
    const int* __restrict__ label)
{
    __shared__ float As[KT * ASTRIDE];   // As[kk][i]  (reused for redFP)
    __shared__ float Bs[KT * ASTRIDE];   // Bs[kk][j]  (reused for redCN)

    const int i0 = blockIdx.y * 128;
    const int j0 = blockIdx.x * 128;
    const int t  = threadIdx.x;
    const int tx = t & 15;    // 16 col-groups of 8
    const int ty = t >> 4;    // 16 row-groups of 8

    float acc[8][8];
#pragma unroll
    for (int r = 0; r < 8; r++)
#pragma unroll
        for (int c = 0; c < 8; c++) acc[r][c] = 0.f;

    for (int k0 = 0; k0 < DD; k0 += KT) {
#pragma unroll
        for (int s = 0; s < 4; s++) {
            int v = t + s * 256;          // 0..1023
            int r = v >> 3, q = v & 7;    // row, float4-chunk within 32-wide k-slice
            float4 av = *reinterpret_cast<const float4*>(sem + (size_t)(i0 + r) * DD + k0 + q * 4);
            float4 bv = *reinterpret_cast<const float4*>(x   + (size_t)(j0 + r) * DD + k0 + q * 4);
            As[(q * 4 + 0) * ASTRIDE + r] = av.x;
            As[(q * 4 + 1) * ASTRIDE + r] = av.y;
            As[(q * 4 + 2) * ASTRIDE + r] = av.z;
            As[(q * 4 + 3) * ASTRIDE + r] = av.w;
            Bs[(q * 4 + 0) * ASTRIDE + r] = bv.x;
            Bs[(q * 4 + 1) * ASTRIDE + r] = bv.y;
            Bs[(q * 4 + 2) * ASTRIDE + r] = bv.z;
            Bs[(q * 4 + 3) * ASTRIDE + r] = bv.w;
        }
        __syncthreads();
#pragma unroll
        for (int kk = 0; kk < KT; kk++) {
            float a[8], b[8];
#pragma unroll
            for (int r = 0; r < 8; r++) a[r] = As[kk * ASTRIDE + ty * 8 + r];
#pragma unroll
            for (int c = 0; c < 8; c++) b[c] = Bs[kk * ASTRIDE + tx * 8 + c];
#pragma unroll
            for (int r = 0; r < 8; r++)
#pragma unroll
                for (int c = 0; c < 8; c++) acc[r][c] = fmaf(a[r], b[c], acc[r][c]);
        }
        __syncthreads();
    }

    // Epilogue: dist -> masked max / min, per-thread over its 8x8 microtile.
    int   li[8], lj[8];
    float sn[8], xn[8];
#pragma unroll
    for (int r = 0; r < 8; r++) {
        int gi = i0 + ty * 8 + r;
        li[r] = label[gi];
        sn[r] = g_semnorm[gi];
    }
#pragma unroll
    for (int c = 0; c < 8; c++) {
        int gj = j0 + tx * 8 + c;
        lj[c] = label[gj];
        xn[c] = g_xnorm[gj];
    }

    const float DEPS = (float)DD * 1e-16f;
    float fpm[8], cnm[8];
#pragma unroll
    for (int r = 0; r < 8; r++) {
        int gi = i0 + ty * 8 + r;
        float fmx = 0.f, cmn = 3.402823466e38f;
#pragma unroll
        for (int c = 0; c < 8; c++) {
            int gj = j0 + tx * 8 + c;
            float sq   = sn[r] + xn[c] - 2.0f * acc[r][c];
            float dist = sqrtf(fmaxf(sq, 0.f) + DEPS);
            bool  same = (li[r] == lj[c]);
            float fpc  = (same && (gi != gj)) ? dist : 0.f;
            float cnc  = same ? (dist + 1e8f) : dist;
            fmx = fmaxf(fmx, fpc);
            cmn = fminf(cmn, cnc);
        }
        fpm[r] = fmx; cnm[r] = cmn;
    }

    // Cross-thread (16 tx) reduction via smem (reuse As/Bs), then global atomics.
#pragma unroll
    for (int r = 0; r < 8; r++) {
        As[(ty * 8 + r) * 16 + tx] = fpm[r];
        Bs[(ty * 8 + r) * 16 + tx] = cnm[r];
    }
    __syncthreads();
    if (t < 128) {
        float fmx = 0.f, cmn = 3.402823466e38f;
#pragma unroll
        for (int u = 0; u < 16; u++) {
            fmx = fmaxf(fmx, As[t * 16 + u]);
            cmn = fminf(cmn, Bs[t * 16 + u]);
        }
        // all values >= 0 -> uint ordering == float ordering
        atomicMax(&g_fp_bits[i0 + t], __float_as_uint(fmx));
        atomicMin(&g_cn_bits[i0 + t], __float_as_uint(cmn));
    }
}

// ---------------------------------------------------------------------------
__global__ void softplus_kernel(float* __restrict__ out) {
    int i = blockIdx.x * blockDim.x + threadIdx.x;
    if (i < NN) {
        float fp = __uint_as_float(g_fp_bits[i]);
        float cn = __uint_as_float(g_cn_bits[i]);
        float z  = fp - cn;
        out[i] = fmaxf(z, 0.f) + log1pf(expf(-fabsf(z)));
    }
}

// ---------------------------------------------------------------------------
extern "C" void kernel_launch(void* const* d_in, const int* in_sizes, int n_in,
                              void* d_out, int out_size)
{
    const float* x     = (const float*)d_in[0];   // [N, D]
    const float* wv    = (const float*)d_in[1];   // [N, WV]
    const int*   label = (const int*)  d_in[2];   // [N]
    const float* alpha = (const float*)d_in[3];   // [N, 1]
    const float* Wm    = (const float*)d_in[4];   // [D, WV]
    const float* bias  = (const float*)d_in[5];   // [D]

    float* out = (float*)d_out;        // [N] diff, then [N, D] sem
    float* sem = out + NN;

    init_kernel<<<(NN + 255) / 256, 256>>>();
    sem_kernel<<<NN / 64, 256>>>(wv, Wm, bias, x, alpha, sem);
    norms_kernel<<<(2 * NN * 32) / 256, 256>>>(x, sem);
    dim3 grid(NN / 128, NN / 128);
    dist_kernel<<<grid, 256>>>(sem, x, label);
    softplus_kernel<<<(NN + 255) / 256, 256>>>(out);
}

// round 8
// speedup vs baseline: 2.4172x; 2.4172x over previous
#include <cuda_runtime.h>
#include <cuda_bf16.h>
#include <math.h>
#include <stdint.h>

#define NN 8192
#define DD 128
#define NTILE 64           // 8192/128 tiles
#define TSTRIDE 272        // 128 bf16 cols = 256B data + 16B pad (conflict-free ldmatrix)
#define TILE_B (128 * TSTRIDE)   // 34816 bytes per tile image
#define JG 8               // j-groups; each CTA loops 8 j-tiles

// ---------------- device globals ----------------
__device__ char g_semhi[NTILE * TILE_B];
__device__ char g_semlo[NTILE * TILE_B];
__device__ char g_xhi[NTILE * TILE_B];
__device__ char g_xlo[NTILE * TILE_B];
__device__ float g_semnorm[NN];
__device__ float g_xnorm[NN];
__device__ unsigned g_mp[NN];   // max over positives of u = xn - 2*dot (monotone-mapped bits)
__device__ unsigned g_md[NN];   // min over diff-class of u
__device__ unsigned g_ms[NN];   // min over same-class of u

// ---------------- helpers ----------------
__device__ __forceinline__ unsigned fmap(float f) {
    unsigned b = __float_as_uint(f);
    return (b & 0x80000000u) ? ~b : (b | 0x80000000u);
}
__device__ __forceinline__ float funmap(unsigned m) {
    unsigned b = (m & 0x80000000u) ? (m & 0x7FFFFFFFu) : ~m;
    return __uint_as_float(b);
}
__device__ __forceinline__ uint32_t smem_u32(const void* p) {
    uint32_t a;
    asm("{ .reg .u64 t; cvta.to.shared.u64 t, %1; cvt.u32.u64 %0, t; }" : "=r"(a) : "l"(p));
    return a;
}
__device__ __forceinline__ uint64_t gaddr(const void* p) {
    uint64_t a;
    asm("cvta.to.global.u64 %0, %1;" : "=l"(a) : "l"(p));
    return a;
}
#define MBAR_INIT(a, c)   asm volatile("mbarrier.init.shared.b64 [%0], %1;" :: "r"(a), "r"(c) : "memory")
#define MBAR_EXPECT(a, b) asm volatile("mbarrier.arrive.expect_tx.shared.b64 _, [%0], %1;" :: "r"(a), "r"(b) : "memory")
__device__ __forceinline__ void mbar_wait(uint32_t mbar, uint32_t parity) {
    asm volatile(
        "{\n .reg .pred P1;\n"
        "WL_%=:\n mbarrier.try_wait.parity.acquire.cta.shared::cta.b64 P1, [%0], %1, 0x989680;\n"
        "@P1 bra.uni WD_%=;\n bra.uni WL_%=;\n WD_%=:\n}"
        :: "r"(mbar), "r"(parity) : "memory");
}
__device__ __forceinline__ void bulk_g2s(uint32_t dst, uint64_t src, uint32_t bytes, uint32_t mbar) {
    asm volatile("cp.async.bulk.shared::cta.global.mbarrier::complete_tx::bytes [%0], [%1], %2, [%3];"
                 :: "r"(dst), "l"(src), "r"(bytes), "r"(mbar) : "memory");
}
__device__ __forceinline__ void ldm_x4(unsigned* r, uint32_t addr) {
    asm volatile("ldmatrix.sync.aligned.m8n8.x4.shared.b16 {%0,%1,%2,%3}, [%4];"
                 : "=r"(r[0]), "=r"(r[1]), "=r"(r[2]), "=r"(r[3]) : "r"(addr));
}
__device__ __forceinline__ void mma_bf16(float* c, const unsigned* a, const unsigned* b) {
    asm volatile("mma.sync.aligned.m16n8k16.row.col.f32.bf16.bf16.f32 "
                 "{%0,%1,%2,%3}, {%4,%5,%6,%7}, {%8,%9}, {%0,%1,%2,%3};"
                 : "+f"(c[0]), "+f"(c[1]), "+f"(c[2]), "+f"(c[3])
                 : "r"(a[0]), "r"(a[1]), "r"(a[2]), "r"(a[3]), "r"(b[0]), "r"(b[1]));
}

// ---------------------------------------------------------------------------
__global__ void init_kernel() {
    int i = blockIdx.x * blockDim.x + threadIdx.x;
    if (i < NN) {
        g_mp[i] = 0u;
        g_md[i] = 0xFFFFFFFFu;
        g_ms[i] = 0xFFFFFFFFu;
    }
}

// ---------------------------------------------------------------------------
// sem = alpha*(wv@W^T + b) + (1-alpha)*x    (proven in R1/R2)
__global__ __launch_bounds__(256) void sem_kernel(
    const float* __restrict__ wv, const float* __restrict__ Wm,
    const float* __restrict__ bias, const float* __restrict__ x,
    const float* __restrict__ alpha, float* __restrict__ sem)
{
    __shared__ float As[64 * 50];
    __shared__ float Ws[50 * 128];
    const int i0 = blockIdx.x * 64;
    const int t = threadIdx.x;
    const int tx = t & 15, ty = t >> 4;
    float acc[4][8];
#pragma unroll
    for (int r = 0; r < 4; r++)
#pragma unroll
        for (int c = 0; c < 8; c++) acc[r][c] = 0.f;
    for (int k0 = 0; k0 < 300; k0 += 50) {
        for (int e = t; e < 64 * 50; e += 256) { int r = e / 50, kk = e % 50; As[e] = wv[(i0 + r) * 300 + k0 + kk]; }
        for (int e = t; e < 50 * 128; e += 256) { int d = e / 50, kk = e % 50; Ws[kk * 128 + d] = Wm[d * 300 + k0 + kk]; }
        __syncthreads();
#pragma unroll 5
        for (int kk = 0; kk < 50; kk++) {
            float a[4], bb[8];
#pragma unroll
            for (int r = 0; r < 4; r++) a[r] = As[(ty * 4 + r) * 50 + kk];
#pragma unroll
            for (int c = 0; c < 8; c++) bb[c] = Ws[kk * 128 + tx * 8 + c];
#pragma unroll
            for (int r = 0; r < 4; r++)
#pragma unroll
                for (int c = 0; c < 8; c++) acc[r][c] = fmaf(a[r], bb[c], acc[r][c]);
        }
        __syncthreads();
    }
#pragma unroll
    for (int r = 0; r < 4; r++) {
        int gi = i0 + ty * 4 + r;
        float al = alpha[gi];
#pragma unroll
        for (int c = 0; c < 8; c++) {
            int gc = tx * 8 + c;
            float v = acc[r][c] + bias[gc];
            sem[gi * DD + gc] = al * v + (1.0f - al) * x[gi * DD + gc];
        }
    }
}

// ---------------------------------------------------------------------------
// fp32 rows -> hi/lo bf16 padded tile images (row stride 272B); plus sq norms.
// One warp per row; rows [0,N)=x, [N,2N)=sem.
__global__ __launch_bounds__(256) void convert_kernel(const float* __restrict__ x,
                                                      const float* __restrict__ sem)
{
    int rowg = blockIdx.x * 8 + (threadIdx.x >> 5);
    int lid = threadIdx.x & 31;
    const float* src;
    char *hi_img, *lo_img;
    int row;
    if (rowg < NN) { src = x; hi_img = g_xhi; lo_img = g_xlo; row = rowg; }
    else { src = sem; hi_img = g_semhi; lo_img = g_semlo; row = rowg - NN; }

    float4 v = reinterpret_cast<const float4*>(src + (size_t)row * DD)[lid];
    float s = v.x * v.x + v.y * v.y + v.z * v.z + v.w * v.w;
#pragma unroll
    for (int o = 16; o > 0; o >>= 1) s += __shfl_xor_sync(0xFFFFFFFFu, s, o);

    float f[4] = {v.x, v.y, v.z, v.w};
    unsigned short h[4], l[4];
#pragma unroll
    for (int q = 0; q < 4; q++) {
        __nv_bfloat16 hb = __float2bfloat16(f[q]);
        __nv_bfloat16 lb = __float2bfloat16(f[q] - __bfloat162float(hb));
        h[q] = __bfloat16_as_ushort(hb);
        l[q] = __bfloat16_as_ushort(lb);
    }
    unsigned long long hp = (unsigned long long)h[0] | ((unsigned long long)h[1] << 16) |
                            ((unsigned long long)h[2] << 32) | ((unsigned long long)h[3] << 48);
    unsigned long long lp = (unsigned long long)l[0] | ((unsigned long long)l[1] << 16) |
                            ((unsigned long long)l[2] << 32) | ((unsigned long long)l[3] << 48);

    int tile = row >> 7, rr = row & 127;
    size_t off = (size_t)tile * TILE_B + (size_t)rr * TSTRIDE + lid * 8;
    *reinterpret_cast<unsigned long long*>(hi_img + off) = hp;
    *reinterpret_cast<unsigned long long*>(lo_img + off) = lp;

    if (lid == 0) {
        if (rowg < NN) g_xnorm[row] = s;
        else g_semnorm[row] = s;
    }
}

// ---------------------------------------------------------------------------
// Fused bf16 mma.sync pairwise GEMM + batch-hard reduction.
// grid (JG=8, NTILE=64), 256 threads (8 warps, warp grid 4x2 -> 32x64 warp tile).
#define SM_AHI 0
#define SM_ALO TILE_B
#define SM_B(buf, part) (2 * TILE_B + (buf) * 2 * TILE_B + (part) * TILE_B)
#define SM_CTRL (6 * TILE_B)
#define SM_MBLD(s) (SM_CTRL + (s) * 8)
#define SM_JINFO (SM_CTRL + 16)
#define SM_TOTAL (SM_CTRL + 16 + 1024)

__global__ void __launch_bounds__(256, 1) dist_kernel(const int* __restrict__ label)
{
    extern __shared__ char smem[];
    const uint32_t sb = smem_u32(smem);
    const int t = threadIdx.x;
    const int lane = t & 31, wid = t >> 5;
    const int wm = wid & 3, wn = wid >> 2;      // warp tile (wm*32 rows, wn*64 cols)
    const int itile = blockIdx.y, jg = blockIdx.x;

    if (t == 0) {
        MBAR_INIT(sb + SM_MBLD(0), 1);
        MBAR_INIT(sb + SM_MBLD(1), 1);
    }
    __syncthreads();

    if (t == 0) {
        MBAR_EXPECT(sb + SM_MBLD(0), 4u * TILE_B);
        bulk_g2s(sb + SM_AHI, gaddr(g_semhi + (size_t)itile * TILE_B), TILE_B, sb + SM_MBLD(0));
        bulk_g2s(sb + SM_ALO, gaddr(g_semlo + (size_t)itile * TILE_B), TILE_B, sb + SM_MBLD(0));
        size_t jt0 = (size_t)(jg * 8) * TILE_B;
        bulk_g2s(sb + SM_B(0, 0), gaddr(g_xhi + jt0), TILE_B, sb + SM_MBLD(0));
        bulk_g2s(sb + SM_B(0, 1), gaddr(g_xlo + jt0), TILE_B, sb + SM_MBLD(0));
    }

    // per-thread identity: 4 distinct rows (mt 0/1 x row-half 0/1)
    const int q = lane & 3, rquad = lane >> 2;
    int gi4[4];
    int li[4];
#pragma unroll
    for (int s = 0; s < 4; s++) {
        gi4[s] = itile * 128 + wm * 32 + (s >> 1) * 16 + (s & 1) * 8 + rquad;
        li[s] = label[gi4[s]];
    }
    float mpos[4], msame[4], mdiff[4];
#pragma unroll
    for (int s = 0; s < 4; s++) { mpos[s] = -3.0e38f; msame[s] = 3.0e38f; mdiff[s] = 3.0e38f; }

    // ldmatrix base addresses
    const int lr = lane & 7, grp = lane >> 3;
    const uint32_t aOff0 = (uint32_t)(wm * 32 + (grp & 1) * 8 + lr) * TSTRIDE + (grp >> 1) * 16;
    const uint32_t aOff1 = aOff0 + 16u * TSTRIDE;
    const uint32_t pAhi0 = sb + SM_AHI + aOff0, pAhi1 = sb + SM_AHI + aOff1;
    const uint32_t pAlo0 = sb + SM_ALO + aOff0, pAlo1 = sb + SM_ALO + aOff1;
    const uint32_t bOff = (uint32_t)(wn * 64 + ((grp >> 1) & 1) * 8 + lr) * TSTRIDE + (grp & 1) * 16;

    uint2* jinfo = (uint2*)(smem + SM_JINFO);
    const uint4* jinfo4 = (const uint4*)(smem + SM_JINFO);

    for (int j = 0; j < 8; j++) {
        const int jt = jg * 8 + j;
        const int buf = j & 1;

        mbar_wait(sb + SM_MBLD(buf), (unsigned)((j >> 1) & 1));
        if (t < 128) {
            uint2 ji;
            ji.x = __float_as_uint(g_xnorm[jt * 128 + t]);
            ji.y = (unsigned)label[jt * 128 + t];
            jinfo[t] = ji;
        }
        __syncthreads();  // jinfo visible; all warps done with previous mainloop -> nb free

        if (t == 0 && j + 1 < 8) {
            int nb = (j + 1) & 1;
            MBAR_EXPECT(sb + SM_MBLD(nb), 2u * TILE_B);
            size_t jn = (size_t)(jt + 1) * TILE_B;
            bulk_g2s(sb + SM_B(nb, 0), gaddr(g_xhi + jn), TILE_B, sb + SM_MBLD(nb));
            bulk_g2s(sb + SM_B(nb, 1), gaddr(g_xlo + jn), TILE_B, sb + SM_MBLD(nb));
        }

        // ---- mainloop: acc = Ahi*Bhi + Ahi*Blo + Alo*Bhi over K=128 ----
        float acc[2][8][4];
#pragma unroll
        for (int mt = 0; mt < 2; mt++)
#pragma unroll
            for (int nt = 0; nt < 8; nt++)
#pragma unroll
                for (int e = 0; e < 4; e++) acc[mt][nt][e] = 0.f;

        const uint32_t pBhi = sb + SM_B(buf, 0) + bOff;
        const uint32_t pBlo = sb + SM_B(buf, 1) + bOff;
#pragma unroll
        for (int ks = 0; ks < 8; ks++) {
            unsigned ah[2][4], al[2][4];
            ldm_x4(ah[0], pAhi0 + ks * 32);
            ldm_x4(ah[1], pAhi1 + ks * 32);
            ldm_x4(al[0], pAlo0 + ks * 32);
            ldm_x4(al[1], pAlo1 + ks * 32);
#pragma unroll
            for (int np = 0; np < 4; np++) {
                unsigned bh[4], bl[4];
                ldm_x4(bh, pBhi + np * (16 * TSTRIDE) + ks * 32);
                ldm_x4(bl, pBlo + np * (16 * TSTRIDE) + ks * 32);
#pragma unroll
                for (int mt = 0; mt < 2; mt++) {
                    mma_bf16(acc[mt][2 * np],     ah[mt], bh);
                    mma_bf16(acc[mt][2 * np + 1], ah[mt], bh + 2);
                    mma_bf16(acc[mt][2 * np],     ah[mt], bl);
                    mma_bf16(acc[mt][2 * np + 1], ah[mt], bl + 2);
                    mma_bf16(acc[mt][2 * np],     al[mt], bh);
                    mma_bf16(acc[mt][2 * np + 1], al[mt], bh + 2);
                }
            }
        }

        // ---- epilogue: u = xn[j] - 2*dot, masked max/min into registers ----
#pragma unroll
        for (int nt = 0; nt < 8; nt++) {
            uint4 v = jinfo4[wn * 32 + nt * 4 + q];    // (xn[jc],lab[jc],xn[jc+1],lab[jc+1])
            float xn0 = __uint_as_float(v.x), xn1 = __uint_as_float(v.z);
            int lb0 = (int)v.y, lb1 = (int)v.w;
            int gj0 = jt * 128 + wn * 64 + nt * 8 + q * 2;
#pragma unroll
            for (int mt = 0; mt < 2; mt++) {
                const float* a4 = acc[mt][nt];
                int s0 = mt * 2, s1 = mt * 2 + 1;
                float u;
                u = fmaf(-2.f, a4[0], xn0);
                if (lb0 == li[s0]) { msame[s0] = fminf(msame[s0], u); if (gi4[s0] != gj0) mpos[s0] = fmaxf(mpos[s0], u); }
                else mdiff[s0] = fminf(mdiff[s0], u);
                u = fmaf(-2.f, a4[1], xn1);
                if (lb1 == li[s0]) { msame[s0] = fminf(msame[s0], u); if (gi4[s0] != gj0 + 1) mpos[s0] = fmaxf(mpos[s0], u); }
                else mdiff[s0] = fminf(mdiff[s0], u);
                u = fmaf(-2.f, a4[2], xn0);
                if (lb0 == li[s1]) { msame[s1] = fminf(msame[s1], u); if (gi4[s1] != gj0) mpos[s1] = fmaxf(mpos[s1], u); }
                else mdiff[s1] = fminf(mdiff[s1], u);
                u = fmaf(-2.f, a4[3], xn1);
                if (lb1 == li[s1]) { msame[s1] = fminf(msame[s1], u); if (gi4[s1] != gj0 + 1) mpos[s1] = fmaxf(mpos[s1], u); }
                else mdiff[s1] = fminf(mdiff[s1], u);
            }
        }
        __syncthreads();   // epilogue done before next iter rewrites jinfo
    }

    // quad reduction (4 lanes share the same rows), then one atomic triple per row
#pragma unroll
    for (int s = 0; s < 4; s++) {
#pragma unroll
        for (int o = 1; o <= 2; o <<= 1) {
            mpos[s] = fmaxf(mpos[s], __shfl_xor_sync(0xFFFFFFFFu, mpos[s], o));
            msame[s] = fminf(msame[s], __shfl_xor_sync(0xFFFFFFFFu, msame[s], o));
            mdiff[s] = fminf(mdiff[s], __shfl_xor_sync(0xFFFFFFFFu, mdiff[s], o));
        }
        if (q == 0) {
            if (mpos[s] > -2.9e38f) atomicMax(&g_mp[gi4[s]], fmap(mpos[s]));
            atomicMin(&g_md[gi4[s]], fmap(mdiff[s]));
            atomicMin(&g_ms[gi4[s]], fmap(msame[s]));
        }
    }
}

// ---------------------------------------------------------------------------
__global__ void final_kernel(float* __restrict__ out) {
    int i = blockIdx.x * blockDim.x + threadIdx.x;
    if (i >= NN) return;
    const float DEPS = (float)DD * 1e-16f;
    float sn = g_semnorm[i];
    unsigned mp = g_mp[i], md = g_md[i], ms = g_ms[i];
    float fp = (mp == 0u) ? 0.f : sqrtf(fmaxf(sn + funmap(mp), 0.f) + DEPS);
    float d1 = (md == 0xFFFFFFFFu) ? 3.0e38f : sqrtf(fmaxf(sn + funmap(md), 0.f) + DEPS);
    float d2 = (ms == 0xFFFFFFFFu) ? 3.0e38f : sqrtf(fmaxf(sn + funmap(ms), 0.f) + DEPS) + 1e8f;
    float cn = fminf(d1, d2);
    float z = fp - cn;
    out[i] = fmaxf(z, 0.f) + log1pf(expf(-fabsf(z)));
}

// ---------------------------------------------------------------------------
extern "C" void kernel_launch(void* const* d_in, const int* in_sizes, int n_in,
                              void* d_out, int out_size)
{
    const float* x = (const float*)d_in[0];
    const float* wv = (const float*)d_in[1];
    const int* label = (const int*)d_in[2];
    const float* alpha = (const float*)d_in[3];
    const float* Wm = (const float*)d_in[4];
    const float* bias = (const float*)d_in[5];

    float* out = (float*)d_out;       // [N] diff, then [N,D] sem
    float* sem = out + NN;

    cudaFuncSetAttribute(dist_kernel, cudaFuncAttributeMaxDynamicSharedMemorySize, SM_TOTAL);

    init_kernel<<<(NN + 255) / 256, 256>>>();
    sem_kernel<<<NN / 64, 256>>>(wv, Wm, bias, x, alpha, sem);
    convert_kernel<<<(2 * NN) / 8, 256>>>(x, sem);
    dim3 grid(JG, NTILE);
    dist_kernel<<<grid, 256, SM_TOTAL>>>(label);
    final_kernel<<<(NN + 255) / 256, 256>>>(out);
}

// round 9
// speedup vs baseline: 2.5791x; 1.0670x over previous
#include <cuda_runtime.h>
#include <cuda_bf16.h>
#include <math.h>
#include <stdint.h>

#define NN 8192
#define DD 128
#define NTILE 64           // 8192/128 tiles
#define TSTRIDE 272        // 128 bf16 cols = 256B data + 16B pad (conflict-free ldmatrix)
#define TILE_B (128 * TSTRIDE)   // 34816 bytes per tile image
#define NJG 16             // j-groups per i-tile
#define JPC 4              // j-tiles per CTA

// ---------------- device globals ----------------
__device__ char g_semhi[NTILE * TILE_B];
__device__ char g_semlo[NTILE * TILE_B];
__device__ char g_xhi[NTILE * TILE_B];
__device__ char g_xlo[NTILE * TILE_B];
__device__ float g_semnorm[NN];
__device__ float g_xnorm[NN];
__device__ unsigned g_mp[NN];   // max over positives of u = xn - 2*dot (monotone-mapped bits)
__device__ unsigned g_md[NN];   // min over diff-class of u
__device__ unsigned g_ms[NN];   // min over same-class of u

// ---------------- helpers ----------------
__device__ __forceinline__ unsigned fmap(float f) {
    unsigned b = __float_as_uint(f);
    return (b & 0x80000000u) ? ~b : (b | 0x80000000u);
}
__device__ __forceinline__ float funmap(unsigned m) {
    unsigned b = (m & 0x80000000u) ? (m & 0x7FFFFFFFu) : ~m;
    return __uint_as_float(b);
}
__device__ __forceinline__ uint32_t smem_u32(const void* p) {
    uint32_t a;
    asm("{ .reg .u64 t; cvta.to.shared.u64 t, %1; cvt.u32.u64 %0, t; }" : "=r"(a) : "l"(p));
    return a;
}
__device__ __forceinline__ uint64_t gaddr(const void* p) {
    uint64_t a;
    asm("cvta.to.global.u64 %0, %1;" : "=l"(a) : "l"(p));
    return a;
}
#define MBAR_INIT(a, c)   asm volatile("mbarrier.init.shared.b64 [%0], %1;" :: "r"(a), "r"(c) : "memory")
#define MBAR_EXPECT(a, b) asm volatile("mbarrier.arrive.expect_tx.shared.b64 _, [%0], %1;" :: "r"(a), "r"(b) : "memory")
__device__ __forceinline__ void mbar_wait(uint32_t mbar, uint32_t parity) {
    asm volatile(
        "{\n .reg .pred P1;\n"
        "WL_%=:\n mbarrier.try_wait.parity.acquire.cta.shared::cta.b64 P1, [%0], %1, 0x989680;\n"
        "@P1 bra.uni WD_%=;\n bra.uni WL_%=;\n WD_%=:\n}"
        :: "r"(mbar), "r"(parity) : "memory");
}
__device__ __forceinline__ void bulk_g2s(uint32_t dst, uint64_t src, uint32_t bytes, uint32_t mbar) {
    asm volatile("cp.async.bulk.shared::cta.global.mbarrier::complete_tx::bytes [%0], [%1], %2, [%3];"
                 :: "r"(dst), "l"(src), "r"(bytes), "r"(mbar) : "memory");
}
__device__ __forceinline__ void ldm_x4(unsigned* r, uint32_t addr) {
    asm volatile("ldmatrix.sync.aligned.m8n8.x4.shared.b16 {%0,%1,%2,%3}, [%4];"
                 : "=r"(r[0]), "=r"(r[1]), "=r"(r[2]), "=r"(r[3]) : "r"(addr));
}
__device__ __forceinline__ void mma_bf16(float* c, const unsigned* a, const unsigned* b) {
    asm volatile("mma.sync.aligned.m16n8k16.row.col.f32.bf16.bf16.f32 "
                 "{%0,%1,%2,%3}, {%4,%5,%6,%7}, {%8,%9}, {%0,%1,%2,%3};"
                 : "+f"(c[0]), "+f"(c[1]), "+f"(c[2]), "+f"(c[3])
                 : "r"(a[0]), "r"(a[1]), "r"(a[2]), "r"(a[3]), "r"(b[0]), "r"(b[1]));
}

// ---------------------------------------------------------------------------
// sem = alpha*(wv@W^T + b) + (1-alpha)*x
__global__ __launch_bounds__(256) void sem_kernel(
    const float* __restrict__ wv, const float* __restrict__ Wm,
    const float* __restrict__ bias, const float* __restrict__ x,
    const float* __restrict__ alpha, float* __restrict__ sem)
{
    __shared__ float As[64 * 50];
    __shared__ float Ws[50 * 128];
    const int i0 = blockIdx.x * 64;
    const int t = threadIdx.x;
    const int tx = t & 15, ty = t >> 4;
    float acc[4][8];
#pragma unroll
    for (int r = 0; r < 4; r++)
#pragma unroll
        for (int c = 0; c < 8; c++) acc[r][c] = 0.f;
    for (int k0 = 0; k0 < 300; k0 += 50) {
        for (int e = t; e < 64 * 50; e += 256) { int r = e / 50, kk = e % 50; As[e] = wv[(i0 + r) * 300 + k0 + kk]; }
        for (int e = t; e < 50 * 128; e += 256) { int d = e / 50, kk = e % 50; Ws[kk * 128 + d] = Wm[d * 300 + k0 + kk]; }
        __syncthreads();
#pragma unroll 5
        for (int kk = 0; kk < 50; kk++) {
            float a[4], bb[8];
#pragma unroll
            for (int r = 0; r < 4; r++) a[r] = As[(ty * 4 + r) * 50 + kk];
#pragma unroll
            for (int c = 0; c < 8; c++) bb[c] = Ws[kk * 128 + tx * 8 + c];
#pragma unroll
            for (int r = 0; r < 4; r++)
#pragma unroll
                for (int c = 0; c < 8; c++) acc[r][c] = fmaf(a[r], bb[c], acc[r][c]);
        }
        __syncthreads();
    }
#pragma unroll
    for (int r = 0; r < 4; r++) {
        int gi = i0 + ty * 4 + r;
        float al = alpha[gi];
#pragma unroll
        for (int c = 0; c < 8; c++) {
            int gc = tx * 8 + c;
            float v = acc[r][c] + bias[gc];
            sem[gi * DD + gc] = al * v + (1.0f - al) * x[gi * DD + gc];
        }
    }
}

// ---------------------------------------------------------------------------
// fp32 rows -> hi/lo bf16 padded tile images; plus sq norms; plus reduction init.
// One warp per row; rows [0,N)=x, [N,2N)=sem.
__global__ __launch_bounds__(256) void convert_kernel(const float* __restrict__ x,
                                                      const float* __restrict__ sem)
{
    int gtid = blockIdx.x * 256 + threadIdx.x;
    if (gtid < NN) {           // fused init of reduction cells
        g_mp[gtid] = 0u;
        g_md[gtid] = 0xFFFFFFFFu;
        g_ms[gtid] = 0xFFFFFFFFu;
    }

    int rowg = blockIdx.x * 8 + (threadIdx.x >> 5);
    int lid = threadIdx.x & 31;
    const float* src;
    char *hi_img, *lo_img;
    int row;
    if (rowg < NN) { src = x; hi_img = g_xhi; lo_img = g_xlo; row = rowg; }
    else { src = sem; hi_img = g_semhi; lo_img = g_semlo; row = rowg - NN; }

    float4 v = reinterpret_cast<const float4*>(src + (size_t)row * DD)[lid];
    float s = v.x * v.x + v.y * v.y + v.z * v.z + v.w * v.w;
#pragma unroll
    for (int o = 16; o > 0; o >>= 1) s += __shfl_xor_sync(0xFFFFFFFFu, s, o);

    float f[4] = {v.x, v.y, v.z, v.w};
    unsigned short h[4], l[4];
#pragma unroll
    for (int q = 0; q < 4; q++) {
        __nv_bfloat16 hb = __float2bfloat16(f[q]);
        __nv_bfloat16 lb = __float2bfloat16(f[q] - __bfloat162float(hb));
        h[q] = __bfloat16_as_ushort(hb);
        l[q] = __bfloat16_as_ushort(lb);
    }
    unsigned long long hp = (unsigned long long)h[0] | ((unsigned long long)h[1] << 16) |
                            ((unsigned long long)h[2] << 32) | ((unsigned long long)h[3] << 48);
    unsigned long long lp = (unsigned long long)l[0] | ((unsigned long long)l[1] << 16) |
                            ((unsigned long long)l[2] << 32) | ((unsigned long long)l[3] << 48);

    int tile = row >> 7, rr = row & 127;
    size_t off = (size_t)tile * TILE_B + (size_t)rr * TSTRIDE + lid * 8;
    *reinterpret_cast<unsigned long long*>(hi_img + off) = hp;
    *reinterpret_cast<unsigned long long*>(lo_img + off) = lp;

    if (lid == 0) {
        if (rowg < NN) g_xnorm[row] = s;
        else g_semnorm[row] = s;
    }
}

// ---------------------------------------------------------------------------
// Fused bf16 mma.sync pairwise GEMM + batch-hard reduction.
// grid (NJG=16, NTILE=64), 256 threads (8 warps, warp grid 4x2 -> 32x64 warp tile).
#define SM_AHI 0
#define SM_ALO TILE_B
#define SM_B(buf, part) (2 * TILE_B + (buf) * 2 * TILE_B + (part) * TILE_B)
#define SM_CTRL (6 * TILE_B)
#define SM_MBLD(s) (SM_CTRL + (s) * 8)
#define SM_JINFO (SM_CTRL + 16)
#define SM_TOTAL (SM_CTRL + 16 + 1024)

__global__ void __launch_bounds__(256, 1) dist_kernel(const int* __restrict__ label)
{
    extern __shared__ char smem[];
    const uint32_t sb = smem_u32(smem);
    const int t = threadIdx.x;
    const int lane = t & 31, wid = t >> 5;
    const int wm = wid & 3, wn = wid >> 2;      // warp tile (wm*32 rows, wn*64 cols)
    const int itile = blockIdx.y, jg = blockIdx.x;

    if (t == 0) {
        MBAR_INIT(sb + SM_MBLD(0), 1);
        MBAR_INIT(sb + SM_MBLD(1), 1);
    }
    __syncthreads();

    if (t == 0) {
        MBAR_EXPECT(sb + SM_MBLD(0), 4u * TILE_B);
        bulk_g2s(sb + SM_AHI, gaddr(g_semhi + (size_t)itile * TILE_B), TILE_B, sb + SM_MBLD(0));
        bulk_g2s(sb + SM_ALO, gaddr(g_semlo + (size_t)itile * TILE_B), TILE_B, sb + SM_MBLD(0));
        size_t jt0 = (size_t)(jg * JPC) * TILE_B;
        bulk_g2s(sb + SM_B(0, 0), gaddr(g_xhi + jt0), TILE_B, sb + SM_MBLD(0));
        bulk_g2s(sb + SM_B(0, 1), gaddr(g_xlo + jt0), TILE_B, sb + SM_MBLD(0));
    }

    // per-thread identity: 4 distinct rows (mt 0/1 x row-half 0/1)
    const int q = lane & 3, rquad = lane >> 2;
    int gi4[4];
    int li[4];
#pragma unroll
    for (int s = 0; s < 4; s++) {
        gi4[s] = itile * 128 + wm * 32 + (s >> 1) * 16 + (s & 1) * 8 + rquad;
        li[s] = label[gi4[s]];
    }
    float mpos[4], msame[4], mdiff[4];
#pragma unroll
    for (int s = 0; s < 4; s++) { mpos[s] = -3.0e38f; msame[s] = 3.0e38f; mdiff[s] = 3.0e38f; }

    // ldmatrix base addresses
    const int lr = lane & 7, grp = lane >> 3;
    const uint32_t aOff0 = (uint32_t)(wm * 32 + (grp & 1) * 8 + lr) * TSTRIDE + (grp >> 1) * 16;
    const uint32_t aOff1 = aOff0 + 16u * TSTRIDE;
    const uint32_t pAhi0 = sb + SM_AHI + aOff0, pAhi1 = sb + SM_AHI + aOff1;
    const uint32_t pAlo0 = sb + SM_ALO + aOff0, pAlo1 = sb + SM_ALO + aOff1;
    const uint32_t bOff = (uint32_t)(wn * 64 + ((grp >> 1) & 1) * 8 + lr) * TSTRIDE + (grp & 1) * 16;

    uint2* jinfo = (uint2*)(smem + SM_JINFO);
    const uint4* jinfo4 = (const uint4*)(smem + SM_JINFO);

    for (int j = 0; j < JPC; j++) {
        const int jt = jg * JPC + j;
        const int buf = j & 1;

        mbar_wait(sb + SM_MBLD(buf), (unsigned)((j >> 1) & 1));
        if (t < 128) {
            uint2 ji;
            ji.x = __float_as_uint(g_xnorm[jt * 128 + t]);
            ji.y = (unsigned)label[jt * 128 + t];
            jinfo[t] = ji;
        }
        __syncthreads();  // jinfo visible; all warps done with previous mainloop -> nb free

        if (t == 0 && j + 1 < JPC) {
            int nb = (j + 1) & 1;
            MBAR_EXPECT(sb + SM_MBLD(nb), 2u * TILE_B);
            size_t jn = (size_t)(jt + 1) * TILE_B;
            bulk_g2s(sb + SM_B(nb, 0), gaddr(g_xhi + jn), TILE_B, sb + SM_MBLD(nb));
            bulk_g2s(sb + SM_B(nb, 1), gaddr(g_xlo + jn), TILE_B, sb + SM_MBLD(nb));
        }

        // ---- mainloop: acc = Ahi*Bhi + Ahi*Blo + Alo*Bhi over K=128 ----
        float acc[2][8][4];
#pragma unroll
        for (int mt = 0; mt < 2; mt++)
#pragma unroll
            for (int nt = 0; nt < 8; nt++)
#pragma unroll
                for (int e = 0; e < 4; e++) acc[mt][nt][e] = 0.f;

        const uint32_t pBhi = sb + SM_B(buf, 0) + bOff;
        const uint32_t pBlo = sb + SM_B(buf, 1) + bOff;
#pragma unroll
        for (int ks = 0; ks < 8; ks++) {
            unsigned ah[2][4], al[2][4], bh[4][4], bl[4][4];
            ldm_x4(ah[0], pAhi0 + ks * 32);
            ldm_x4(ah[1], pAhi1 + ks * 32);
            ldm_x4(al[0], pAlo0 + ks * 32);
            ldm_x4(al[1], pAlo1 + ks * 32);
#pragma unroll
            for (int np = 0; np < 4; np++) {
                ldm_x4(bh[np], pBhi + np * (16 * TSTRIDE) + ks * 32);
                ldm_x4(bl[np], pBlo + np * (16 * TSTRIDE) + ks * 32);
            }
            // pass-major issue order: each accumulator re-touched at distance 16
#pragma unroll
            for (int np = 0; np < 4; np++)
#pragma unroll
                for (int mt = 0; mt < 2; mt++) {
                    mma_bf16(acc[mt][2 * np],     ah[mt], bh[np]);
                    mma_bf16(acc[mt][2 * np + 1], ah[mt], bh[np] + 2);
                }
#pragma unroll
            for (int np = 0; np < 4; np++)
#pragma unroll
                for (int mt = 0; mt < 2; mt++) {
                    mma_bf16(acc[mt][2 * np],     ah[mt], bl[np]);
                    mma_bf16(acc[mt][2 * np + 1], ah[mt], bl[np] + 2);
                }
#pragma unroll
            for (int np = 0; np < 4; np++)
#pragma unroll
                for (int mt = 0; mt < 2; mt++) {
                    mma_bf16(acc[mt][2 * np],     al[mt], bh[np]);
                    mma_bf16(acc[mt][2 * np + 1], al[mt], bh[np] + 2);
                }
        }

        // ---- epilogue: u = xn[j] - 2*dot, masked max/min into registers ----
#pragma unroll
        for (int nt = 0; nt < 8; nt++) {
            uint4 v = jinfo4[wn * 32 + nt * 4 + q];    // (xn[jc],lab[jc],xn[jc+1],lab[jc+1])
            float xn0 = __uint_as_float(v.x), xn1 = __uint_as_float(v.z);
            int lb0 = (int)v.y, lb1 = (int)v.w;
            int gj0 = jt * 128 + wn * 64 + nt * 8 + q * 2;
#pragma unroll
            for (int mt = 0; mt < 2; mt++) {
                const float* a4 = acc[mt][nt];
                int s0 = mt * 2, s1 = mt * 2 + 1;
                float u;
                u = fmaf(-2.f, a4[0], xn0);
                if (lb0 == li[s0]) { msame[s0] = fminf(msame[s0], u); if (gi4[s0] != gj0) mpos[s0] = fmaxf(mpos[s0], u); }
                else mdiff[s0] = fminf(mdiff[s0], u);
                u = fmaf(-2.f, a4[1], xn1);
                if (lb1 == li[s0]) { msame[s0] = fminf(msame[s0], u); if (gi4[s0] != gj0 + 1) mpos[s0] = fmaxf(mpos[s0], u); }
                else mdiff[s0] = fminf(mdiff[s0], u);
                u = fmaf(-2.f, a4[2], xn0);
                if (lb0 == li[s1]) { msame[s1] = fminf(msame[s1], u); if (gi4[s1] != gj0) mpos[s1] = fmaxf(mpos[s1], u); }
                else mdiff[s1] = fminf(mdiff[s1], u);
                u = fmaf(-2.f, a4[3], xn1);
                if (lb1 == li[s1]) { msame[s1] = fminf(msame[s1], u); if (gi4[s1] != gj0 + 1) mpos[s1] = fmaxf(mpos[s1], u); }
                else mdiff[s1] = fminf(mdiff[s1], u);
            }
        }
        __syncthreads();   // epilogue done before next iter rewrites jinfo
    }

    // quad reduction (4 lanes share the same rows), then one atomic triple per row
#pragma unroll
    for (int s = 0; s < 4; s++) {
#pragma unroll
        for (int o = 1; o <= 2; o <<= 1) {
            mpos[s] = fmaxf(mpos[s], __shfl_xor_sync(0xFFFFFFFFu, mpos[s], o));
            msame[s] = fminf(msame[s], __shfl_xor_sync(0xFFFFFFFFu, msame[s], o));
            mdiff[s] = fminf(mdiff[s], __shfl_xor_sync(0xFFFFFFFFu, mdiff[s], o));
        }
        if (q == 0) {
            if (mpos[s] > -2.9e38f) atomicMax(&g_mp[gi4[s]], fmap(mpos[s]));
            atomicMin(&g_md[gi4[s]], fmap(mdiff[s]));
            atomicMin(&g_ms[gi4[s]], fmap(msame[s]));
        }
    }
}

// ---------------------------------------------------------------------------
__global__ void final_kernel(float* __restrict__ out) {
    int i = blockIdx.x * blockDim.x + threadIdx.x;
    if (i >= NN) return;
    const float DEPS = (float)DD * 1e-16f;
    float sn = g_semnorm[i];
    unsigned mp = g_mp[i], md = g_md[i], ms = g_ms[i];
    float fp = (mp == 0u) ? 0.f : sqrtf(fmaxf(sn + funmap(mp), 0.f) + DEPS);
    float d1 = (md == 0xFFFFFFFFu) ? 3.0e38f : sqrtf(fmaxf(sn + funmap(md), 0.f) + DEPS);
    float d2 = (ms == 0xFFFFFFFFu) ? 3.0e38f : sqrtf(fmaxf(sn + funmap(ms), 0.f) + DEPS) + 1e8f;
    float cn = fminf(d1, d2);
    float z = fp - cn;
    out[i] = fmaxf(z, 0.f) + log1pf(expf(-fabsf(z)));
}

// ---------------------------------------------------------------------------
extern "C" void kernel_launch(void* const* d_in, const int* in_sizes, int n_in,
                              void* d_out, int out_size)
{
    const float* x = (const float*)d_in[0];
    const float* wv = (const float*)d_in[1];
    const int* label = (const int*)d_in[2];
    const float* alpha = (const float*)d_in[3];
    const float* Wm = (const float*)d_in[4];
    const float* bias = (const float*)d_in[5];

    float* out = (float*)d_out;       // [N] diff, then [N,D] sem
    float* sem = out + NN;

    cudaFuncSetAttribute(dist_kernel, cudaFuncAttributeMaxDynamicSharedMemorySize, SM_TOTAL);

    sem_kernel<<<NN / 64, 256>>>(wv, Wm, bias, x, alpha, sem);
    convert_kernel<<<(2 * NN) / 8, 256>>>(x, sem);
    dim3 grid(NJG, NTILE);
    dist_kernel<<<grid, 256, SM_TOTAL>>>(label);
    final_kernel<<<(NN + 255) / 256, 256>>>(out);
}

// round 11
// speedup vs baseline: 3.1348x; 1.2155x over previous
#include <cuda_runtime.h>
#include <cuda_fp16.h>
#include <math.h>
#include <stdint.h>

#define NN 8192
#define DD 128
#define NTILE 64           // 8192/128 tiles
#define TSTRIDE 272        // 128 fp16 cols = 256B data + 16B pad (conflict-free ldmatrix)
#define TILE_B (128 * TSTRIDE)   // 34816 bytes per tile image
#define NJG 16             // j-groups per i-tile
#define JPC 4              // j-tiles per CTA

// ---------------- device globals ----------------
__device__ char g_semhi[NTILE * TILE_B];
__device__ char g_xhi[NTILE * TILE_B];
__device__ char g_xlo[NTILE * TILE_B];
__device__ float g_semnorm[NN];
__device__ float g_xnorm[NN];
__device__ unsigned g_mp[NN];   // max over positives of u = xn - 2*dot (monotone-mapped bits)
__device__ unsigned g_md[NN];   // min over diff-class of u
__device__ unsigned g_ms[NN];   // min over same-class of u

// ---------------- helpers ----------------
__device__ __forceinline__ unsigned fmap(float f) {
    unsigned b = __float_as_uint(f);
    return (b & 0x80000000u) ? ~b : (b | 0x80000000u);
}
__device__ __forceinline__ float funmap(unsigned m) {
    unsigned b = (m & 0x80000000u) ? (m & 0x7FFFFFFFu) : ~m;
    return __uint_as_float(b);
}
__device__ __forceinline__ uint32_t smem_u32(const void* p) {
    uint32_t a;
    asm("{ .reg .u64 t; cvta.to.shared.u64 t, %1; cvt.u32.u64 %0, t; }" : "=r"(a) : "l"(p));
    return a;
}
__device__ __forceinline__ uint64_t gaddr(const void* p) {
    uint64_t a;
    asm("cvta.to.global.u64 %0, %1;" : "=l"(a) : "l"(p));
    return a;
}
#define MBAR_INIT(a, c)   asm volatile("mbarrier.init.shared.b64 [%0], %1;" :: "r"(a), "r"(c) : "memory")
#define MBAR_EXPECT(a, b) asm volatile("mbarrier.arrive.expect_tx.shared.b64 _, [%0], %1;" :: "r"(a), "r"(b) : "memory")
__device__ __forceinline__ void mbar_wait(uint32_t mbar, uint32_t parity) {
    asm volatile(
        "{\n .reg .pred P1;\n"
        "WL_%=:\n mbarrier.try_wait.parity.acquire.cta.shared::cta.b64 P1, [%0], %1, 0x989680;\n"
        "@P1 bra.uni WD_%=;\n bra.uni WL_%=;\n WD_%=:\n}"
        :: "r"(mbar), "r"(parity) : "memory");
}
__device__ __forceinline__ void bulk_g2s(uint32_t dst, uint64_t src, uint32_t bytes, uint32_t mbar) {
    asm volatile("cp.async.bulk.shared::cta.global.mbarrier::complete_tx::bytes [%0], [%1], %2, [%3];"
                 :: "r"(dst), "l"(src), "r"(bytes), "r"(mbar) : "memory");
}
__device__ __forceinline__ void ldm_x4(unsigned* r, uint32_t addr) {
    asm volatile("ldmatrix.sync.aligned.m8n8.x4.shared.b16 {%0,%1,%2,%3}, [%4];"
                 : "=r"(r[0]), "=r"(r[1]), "=r"(r[2]), "=r"(r[3]) : "r"(addr));
}
__device__ __forceinline__ void mma_f16(float* c, const unsigned* a, const unsigned* b) {
    asm volatile("mma.sync.aligned.m16n8k16.row.col.f32.f16.f16.f32 "
                 "{%0,%1,%2,%3}, {%4,%5,%6,%7}, {%8,%9}, {%0,%1,%2,%3};"
                 : "+f"(c[0]), "+f"(c[1]), "+f"(c[2]), "+f"(c[3])
                 : "r"(a[0]), "r"(a[1]), "r"(a[2]), "r"(a[3]), "r"(b[0]), "r"(b[1]));
}

// ---------------------------------------------------------------------------
// sem = alpha*(wv@W^T + b) + (1-alpha)*x; fused: fp16 tile image, row norms,
// reduction-cell init.
__global__ __launch_bounds__(256) void sem_kernel(
    const float* __restrict__ wv, const float* __restrict__ Wm,
    const float* __restrict__ bias, const float* __restrict__ x,
    const float* __restrict__ alpha, float* __restrict__ sem)
{
    __shared__ float As[64 * 50];
    __shared__ float Ws[50 * 128];
    const int i0 = blockIdx.x * 64;
    const int t = threadIdx.x;
    const int tx = t & 15, ty = t >> 4;

    int gtid = blockIdx.x * 256 + t;     // fused init of reduction cells
    if (gtid < NN) {
        g_mp[gtid] = 0u;
        g_md[gtid] = 0xFFFFFFFFu;
        g_ms[gtid] = 0xFFFFFFFFu;
    }

    float acc[4][8];
#pragma unroll
    for (int r = 0; r < 4; r++)
#pragma unroll
        for (int c = 0; c < 8; c++) acc[r][c] = 0.f;
    for (int k0 = 0; k0 < 300; k0 += 50) {
        for (int e = t; e < 64 * 50; e += 256) { int r = e / 50, kk = e % 50; As[e] = wv[(i0 + r) * 300 + k0 + kk]; }
        for (int e = t; e < 50 * 128; e += 256) { int d = e / 50, kk = e % 50; Ws[kk * 128 + d] = Wm[d * 300 + k0 + kk]; }
        __syncthreads();
#pragma unroll 5
        for (int kk = 0; kk < 50; kk++) {
            float a[4], bb[8];
#pragma unroll
            for (int r = 0; r < 4; r++) a[r] = As[(ty * 4 + r) * 50 + kk];
#pragma unroll
            for (int c = 0; c < 8; c++) bb[c] = Ws[kk * 128 + tx * 8 + c];
#pragma unroll
            for (int r = 0; r < 4; r++)
#pragma unroll
                for (int c = 0; c < 8; c++) acc[r][c] = fmaf(a[r], bb[c], acc[r][c]);
        }
        __syncthreads();
    }
#pragma unroll
    for (int r = 0; r < 4; r++) {
        int gi = i0 + ty * 4 + r;
        float al = alpha[gi];
        float v[8];
        float nrm = 0.f;
        unsigned short hh[8];
#pragma unroll
        for (int c = 0; c < 8; c++) {
            int gc = tx * 8 + c;
            float val = al * (acc[r][c] + bias[gc]) + (1.0f - al) * x[gi * DD + gc];
            v[c] = val;
            nrm = fmaf(val, val, nrm);
            hh[c] = __half_as_ushort(__float2half_rn(val));
        }
        // fp32 sem output (vectorized)
        float4* semv = reinterpret_cast<float4*>(sem + (size_t)gi * DD + tx * 8);
        semv[0] = make_float4(v[0], v[1], v[2], v[3]);
        semv[1] = make_float4(v[4], v[5], v[6], v[7]);
        // fp16 hi image (16B per thread-row)
        int tile = gi >> 7, rr = gi & 127;
        uint4 hp;
        hp.x = (unsigned)hh[0] | ((unsigned)hh[1] << 16);
        hp.y = (unsigned)hh[2] | ((unsigned)hh[3] << 16);
        hp.z = (unsigned)hh[4] | ((unsigned)hh[5] << 16);
        hp.w = (unsigned)hh[6] | ((unsigned)hh[7] << 16);
        *reinterpret_cast<uint4*>(g_semhi + (size_t)tile * TILE_B + (size_t)rr * TSTRIDE + tx * 16) = hp;
        // row norm: reduce over the 16 tx lanes (same half-warp)
#pragma unroll
        for (int o = 1; o <= 8; o <<= 1) nrm += __shfl_xor_sync(0xFFFFFFFFu, nrm, o);
        if (tx == 0) g_semnorm[gi] = nrm;
    }
}

// ---------------------------------------------------------------------------
// fp32 x rows -> hi/lo fp16 padded tile images + sq norms. One warp per row.
__global__ __launch_bounds__(256) void convert_kernel(const float* __restrict__ x)
{
    int row = blockIdx.x * 8 + (threadIdx.x >> 5);
    int lid = threadIdx.x & 31;

    float4 v = reinterpret_cast<const float4*>(x + (size_t)row * DD)[lid];
    float s = v.x * v.x + v.y * v.y + v.z * v.z + v.w * v.w;
#pragma unroll
    for (int o = 16; o > 0; o >>= 1) s += __shfl_xor_sync(0xFFFFFFFFu, s, o);

    float f[4] = {v.x, v.y, v.z, v.w};
    unsigned short h[4], l[4];
#pragma unroll
    for (int q = 0; q < 4; q++) {
        __half hb = __float2half_rn(f[q]);
        __half lb = __float2half_rn(f[q] - __half2float(hb));
        h[q] = __half_as_ushort(hb);
        l[q] = __half_as_ushort(lb);
    }
    unsigned long long hp = (unsigned long long)h[0] | ((unsigned long long)h[1] << 16) |
                            ((unsigned long long)h[2] << 32) | ((unsigned long long)h[3] << 48);
    unsigned long long lp = (unsigned long long)l[0] | ((unsigned long long)l[1] << 16) |
                            ((unsigned long long)l[2] << 32) | ((unsigned long long)l[3] << 48);

    int tile = row >> 7, rr = row & 127;
    size_t off = (size_t)tile * TILE_B + (size_t)rr * TSTRIDE + lid * 8;
    *reinterpret_cast<unsigned long long*>(g_xhi + off) = hp;
    *reinterpret_cast<unsigned long long*>(g_xlo + off) = lp;

    if (lid == 0) g_xnorm[row] = s;
}

// ---------------------------------------------------------------------------
// Fused fp16 mma.sync pairwise GEMM (2-pass: Ahi*Bhi + Ahi*Blo) + batch-hard
// reduction. grid (NJG=16, NTILE=64), 256 threads, warp grid 4x2 (32x64 tile).
#define SM_A 0
#define SM_B(buf, part) (TILE_B + ((buf) * 2 + (part)) * TILE_B)
#define SM_CTRL (5 * TILE_B)
#define SM_MBLD(s) (SM_CTRL + (s) * 8)
#define SM_JINFO (SM_CTRL + 16)
#define SM_TOTAL (SM_CTRL + 16 + 1024)

__global__ void __launch_bounds__(256, 1) dist_kernel(const int* __restrict__ label)
{
    extern __shared__ char smem[];
    const uint32_t sb = smem_u32(smem);
    const int t = threadIdx.x;
    const int lane = t & 31, wid = t >> 5;
    const int wm = wid & 3, wn = wid >> 2;      // warp tile (wm*32 rows, wn*64 cols)
    const int itile = blockIdx.y, jg = blockIdx.x;

    if (t == 0) {
        MBAR_INIT(sb + SM_MBLD(0), 1);
        MBAR_INIT(sb + SM_MBLD(1), 1);
    }
    __syncthreads();

    if (t == 0) {
        MBAR_EXPECT(sb + SM_MBLD(0), 3u * TILE_B);
        bulk_g2s(sb + SM_A, gaddr(g_semhi + (size_t)itile * TILE_B), TILE_B, sb + SM_MBLD(0));
        size_t jt0 = (size_t)(jg * JPC) * TILE_B;
        bulk_g2s(sb + SM_B(0, 0), gaddr(g_xhi + jt0), TILE_B, sb + SM_MBLD(0));
        bulk_g2s(sb + SM_B(0, 1), gaddr(g_xlo + jt0), TILE_B, sb + SM_MBLD(0));
    }

    // per-thread identity: 4 distinct rows (mt 0/1 x row-half 0/1)
    const int q = lane & 3, rquad = lane >> 2;
    int gi4[4];
    int li[4];
#pragma unroll
    for (int s = 0; s < 4; s++) {
        gi4[s] = itile * 128 + wm * 32 + (s >> 1) * 16 + (s & 1) * 8 + rquad;
        li[s] = label[gi4[s]];
    }
    float mpos[4], msame[4], mdiff[4];
#pragma unroll
    for (int s = 0; s < 4; s++) { mpos[s] = -3.0e38f; msame[s] = 3.0e38f; mdiff[s] = 3.0e38f; }

    // ldmatrix base addresses
    const int lr = lane & 7, grp = lane >> 3;
    const uint32_t aOff0 = (uint32_t)(wm * 32 + (grp & 1) * 8 + lr) * TSTRIDE + (grp >> 1) * 16;
    const uint32_t pA0 = sb + SM_A + aOff0;
    const uint32_t pA1 = pA0 + 16u * TSTRIDE;
    const uint32_t bOff = (uint32_t)(wn * 64 + ((grp >> 1) & 1) * 8 + lr) * TSTRIDE + (grp & 1) * 16;

    uint2* jinfo = (uint2*)(smem + SM_JINFO);
    const uint4* jinfo4 = (const uint4*)(smem + SM_JINFO);

    for (int j = 0; j < JPC; j++) {
        const int jt = jg * JPC + j;
        const int buf = j & 1;

        mbar_wait(sb + SM_MBLD(buf), (unsigned)((j >> 1) & 1));
        if (t < 128) {
            uint2 ji;
            ji.x = __float_as_uint(g_xnorm[jt * 128 + t]);
            ji.y = (unsigned)label[jt * 128 + t];
            jinfo[t] = ji;
        }
        __syncthreads();  // jinfo visible; all warps done with previous mainloop -> nb free

        if (t == 0 && j + 1 < JPC) {
            int nb = (j + 1) & 1;
            MBAR_EXPECT(sb + SM_MBLD(nb), 2u * TILE_B);
            size_t jn = (size_t)(jt + 1) * TILE_B;
            bulk_g2s(sb + SM_B(nb, 0), gaddr(g_xhi + jn), TILE_B, sb + SM_MBLD(nb));
            bulk_g2s(sb + SM_B(nb, 1), gaddr(g_xlo + jn), TILE_B, sb + SM_MBLD(nb));
        }

        // ---- mainloop: acc = Ahi*Bhi + Ahi*Blo over K=128 ----
        float acc[2][8][4];
#pragma unroll
        for (int mt = 0; mt < 2; mt++)
#pragma unroll
            for (int nt = 0; nt < 8; nt++)
#pragma unroll
                for (int e = 0; e < 4; e++) acc[mt][nt][e] = 0.f;

        const uint32_t pBhi = sb + SM_B(buf, 0) + bOff;
        const uint32_t pBlo = sb + SM_B(buf, 1) + bOff;
#pragma unroll
        for (int ks = 0; ks < 8; ks++) {
            unsigned ah[2][4], bh[4][4], bl[4][4];
            ldm_x4(ah[0], pA0 + ks * 32);
            ldm_x4(ah[1], pA1 + ks * 32);
#pragma unroll
            for (int np = 0; np < 4; np++) {
                ldm_x4(bh[np], pBhi + np * (16 * TSTRIDE) + ks * 32);
                ldm_x4(bl[np], pBlo + np * (16 * TSTRIDE) + ks * 32);
            }
            // pass-major issue order: each accumulator re-touched at distance 16
#pragma unroll
            for (int np = 0; np < 4; np++)
#pragma unroll
                for (int mt = 0; mt < 2; mt++) {
                    mma_f16(acc[mt][2 * np],     ah[mt], bh[np]);
                    mma_f16(acc[mt][2 * np + 1], ah[mt], bh[np] + 2);
                }
#pragma unroll
            for (int np = 0; np < 4; np++)
#pragma unroll
                for (int mt = 0; mt < 2; mt++) {
                    mma_f16(acc[mt][2 * np],     ah[mt], bl[np]);
                    mma_f16(acc[mt][2 * np + 1], ah[mt], bl[np] + 2);
                }
        }

        // ---- epilogue: u = xn[j] - 2*dot, masked max/min into registers ----
#pragma unroll
        for (int nt = 0; nt < 8; nt++) {
            uint4 v = jinfo4[wn * 32 + nt * 4 + q];    // (xn[jc],lab[jc],xn[jc+1],lab[jc+1])
            float xn0 = __uint_as_float(v.x), xn1 = __uint_as_float(v.z);
            int lb0 = (int)v.y, lb1 = (int)v.w;
            int gj0 = jt * 128 + wn * 64 + nt * 8 + q * 2;
#pragma unroll
            for (int mt = 0; mt < 2; mt++) {
                const float* a4 = acc[mt][nt];
                int s0 = mt * 2, s1 = mt * 2 + 1;
                float u;
                u = fmaf(-2.f, a4[0], xn0);
                if (lb0 == li[s0]) { msame[s0] = fminf(msame[s0], u); if (gi4[s0] != gj0) mpos[s0] = fmaxf(mpos[s0], u); }
                else mdiff[s0] = fminf(mdiff[s0], u);
                u = fmaf(-2.f, a4[1], xn1);
                if (lb1 == li[s0]) { msame[s0] = fminf(msame[s0], u); if (gi4[s0] != gj0 + 1) mpos[s0] = fmaxf(mpos[s0], u); }
                else mdiff[s0] = fminf(mdiff[s0], u);
                u = fmaf(-2.f, a4[2], xn0);
                if (lb0 == li[s1]) { msame[s1] = fminf(msame[s1], u); if (gi4[s1] != gj0) mpos[s1] = fmaxf(mpos[s1], u); }
                else mdiff[s1] = fminf(mdiff[s1], u);
                u = fmaf(-2.f, a4[3], xn1);
                if (lb1 == li[s1]) { msame[s1] = fminf(msame[s1], u); if (gi4[s1] != gj0 + 1) mpos[s1] = fmaxf(mpos[s1], u); }
                else mdiff[s1] = fminf(mdiff[s1], u);
            }
        }
        __syncthreads();   // epilogue done before next iter rewrites jinfo
    }

    // quad reduction (4 lanes share the same rows), then one atomic triple per row
#pragma unroll
    for (int s = 0; s < 4; s++) {
#pragma unroll
        for (int o = 1; o <= 2; o <<= 1) {
            mpos[s] = fmaxf(mpos[s], __shfl_xor_sync(0xFFFFFFFFu, mpos[s], o));
            msame[s] = fminf(msame[s], __shfl_xor_sync(0xFFFFFFFFu, msame[s], o));
            mdiff[s] = fminf(mdiff[s], __shfl_xor_sync(0xFFFFFFFFu, mdiff[s], o));
        }
        if (q == 0) {
            if (mpos[s] > -2.9e38f) atomicMax(&g_mp[gi4[s]], fmap(mpos[s]));
            atomicMin(&g_md[gi4[s]], fmap(mdiff[s]));
            atomicMin(&g_ms[gi4[s]], fmap(msame[s]));
        }
    }
}

// ---------------------------------------------------------------------------
__global__ void final_kernel(float* __restrict__ out) {
    int i = blockIdx.x * blockDim.x + threadIdx.x;
    if (i >= NN) return;
    const float DEPS = (float)DD * 1e-16f;
    float sn = g_semnorm[i];
    unsigned mp = g_mp[i], md = g_md[i], ms = g_ms[i];
    float fp = (mp == 0u) ? 0.f : sqrtf(fmaxf(sn + funmap(mp), 0.f) + DEPS);
    float d1 = (md == 0xFFFFFFFFu) ? 3.0e38f : sqrtf(fmaxf(sn + funmap(md), 0.f) + DEPS);
    float d2 = (ms == 0xFFFFFFFFu) ? 3.0e38f : sqrtf(fmaxf(sn + funmap(ms), 0.f) + DEPS) + 1e8f;
    float cn = fminf(d1, d2);
    float z = fp - cn;
    out[i] = fmaxf(z, 0.f) + log1pf(expf(-fabsf(z)));
}

// ---------------------------------------------------------------------------
extern "C" void kernel_launch(void* const* d_in, const int* in_sizes, int n_in,
                              void* d_out, int out_size)
{
    const float* x = (const float*)d_in[0];
    const float* wv = (const float*)d_in[1];
    const int* label = (const int*)d_in[2];
    const float* alpha = (const float*)d_in[3];
    const float* Wm = (const float*)d_in[4];
    const float* bias = (const float*)d_in[5];

    float* out = (float*)d_out;       // [N] diff, then [N,D] sem
    float* sem = out + NN;

    cudaFuncSetAttribute(dist_kernel, cudaFuncAttributeMaxDynamicSharedMemorySize, SM_TOTAL);

    sem_kernel<<<NN / 64, 256>>>(wv, Wm, bias, x, alpha, sem);
    convert_kernel<<<NN / 8, 256>>>(x);
    dim3 grid(NJG, NTILE);
    dist_kernel<<<grid, 256, SM_TOTAL>>>(label);
    final_kernel<<<(NN + 255) / 256, 256>>>(out);
}

// round 12
// speedup vs baseline: 4.3337x; 1.3824x over previous
#include <cuda_runtime.h>
#include <cuda_fp16.h>
#include <math.h>
#include <stdint.h>

#define NN 8192
#define DD 128
#define NTILE 64           // 8192/128 tiles
#define TSTRIDE 272        // 128 fp16 cols = 256B data + 16B pad (conflict-free ldmatrix)
#define TILE_B (128 * TSTRIDE)   // 34816 bytes per tile image
#define NJG 32             // j-groups per i-tile
#define JPC 2              // j-tiles per CTA

// ---------------- device globals ----------------
__device__ char g_semhi[NTILE * TILE_B];
__device__ char g_xhi[NTILE * TILE_B];
__device__ float g_semnorm[NN];
__device__ float g_xnorm[NN];
__device__ unsigned g_mp[NN];   // max over positives of u = xn - 2*dot (monotone-mapped bits)
__device__ unsigned g_md[NN];   // min over diff-class of u
__device__ unsigned g_ms[NN];   // min over same-class of u

// ---------------- helpers ----------------
__device__ __forceinline__ unsigned fmap(float f) {
    unsigned b = __float_as_uint(f);
    return (b & 0x80000000u) ? ~b : (b | 0x80000000u);
}
__device__ __forceinline__ float funmap(unsigned m) {
    unsigned b = (m & 0x80000000u) ? (m & 0x7FFFFFFFu) : ~m;
    return __uint_as_float(b);
}
__device__ __forceinline__ uint32_t smem_u32(const void* p) {
    uint32_t a;
    asm("{ .reg .u64 t; cvta.to.shared.u64 t, %1; cvt.u32.u64 %0, t; }" : "=r"(a) : "l"(p));
    return a;
}
__device__ __forceinline__ uint64_t gaddr(const void* p) {
    uint64_t a;
    asm("cvta.to.global.u64 %0, %1;" : "=l"(a) : "l"(p));
    return a;
}
#define MBAR_INIT(a, c)   asm volatile("mbarrier.init.shared.b64 [%0], %1;" :: "r"(a), "r"(c) : "memory")
#define MBAR_EXPECT(a, b) asm volatile("mbarrier.arrive.expect_tx.shared.b64 _, [%0], %1;" :: "r"(a), "r"(b) : "memory")
__device__ __forceinline__ void mbar_wait(uint32_t mbar, uint32_t parity) {
    asm volatile(
        "{\n .reg .pred P1;\n"
        "WL_%=:\n mbarrier.try_wait.parity.acquire.cta.shared::cta.b64 P1, [%0], %1, 0x989680;\n"
        "@P1 bra.uni WD_%=;\n bra.uni WL_%=;\n WD_%=:\n}"
        :: "r"(mbar), "r"(parity) : "memory");
}
__device__ __forceinline__ void bulk_g2s(uint32_t dst, uint64_t src, uint32_t bytes, uint32_t mbar) {
    asm volatile("cp.async.bulk.shared::cta.global.mbarrier::complete_tx::bytes [%0], [%1], %2, [%3];"
                 :: "r"(dst), "l"(src), "r"(bytes), "r"(mbar) : "memory");
}
__device__ __forceinline__ void ldm_x4(unsigned* r, uint32_t addr) {
    asm volatile("ldmatrix.sync.aligned.m8n8.x4.shared.b16 {%0,%1,%2,%3}, [%4];"
                 : "=r"(r[0]), "=r"(r[1]), "=r"(r[2]), "=r"(r[3]) : "r"(addr));
}
__device__ __forceinline__ void mma_f16(float* c, const unsigned* a, const unsigned* b) {
    asm volatile("mma.sync.aligned.m16n8k16.row.col.f32.f16.f16.f32 "
                 "{%0,%1,%2,%3}, {%4,%5,%6,%7}, {%8,%9}, {%0,%1,%2,%3};"
                 : "+f"(c[0]), "+f"(c[1]), "+f"(c[2]), "+f"(c[3])
                 : "r"(a[0]), "r"(a[1]), "r"(a[2]), "r"(a[3]), "r"(b[0]), "r"(b[1]));
}

// ---------------------------------------------------------------------------
// sem = alpha*(wv@W^T + b) + (1-alpha)*x; fused: fp16 tile image, row norms,
// reduction-cell init.
__global__ __launch_bounds__(256) void sem_kernel(
    const float* __restrict__ wv, const float* __restrict__ Wm,
    const float* __restrict__ bias, const float* __restrict__ x,
    const float* __restrict__ alpha, float* __restrict__ sem)
{
    __shared__ float As[64 * 50];
    __shared__ float Ws[50 * 128];
    const int i0 = blockIdx.x * 64;
    const int t = threadIdx.x;
    const int tx = t & 15, ty = t >> 4;

    int gtid = blockIdx.x * 256 + t;     // fused init of reduction cells
    if (gtid < NN) {
        g_mp[gtid] = 0u;
        g_md[gtid] = 0xFFFFFFFFu;
        g_ms[gtid] = 0xFFFFFFFFu;
    }

    float acc[4][8];
#pragma unroll
    for (int r = 0; r < 4; r++)
#pragma unroll
        for (int c = 0; c < 8; c++) acc[r][c] = 0.f;
    for (int k0 = 0; k0 < 300; k0 += 50) {
        for (int e = t; e < 64 * 50; e += 256) { int r = e / 50, kk = e % 50; As[e] = wv[(i0 + r) * 300 + k0 + kk]; }
        for (int e = t; e < 50 * 128; e += 256) { int d = e / 50, kk = e % 50; Ws[kk * 128 + d] = Wm[d * 300 + k0 + kk]; }
        __syncthreads();
#pragma unroll 5
        for (int kk = 0; kk < 50; kk++) {
            float a[4], bb[8];
#pragma unroll
            for (int r = 0; r < 4; r++) a[r] = As[(ty * 4 + r) * 50 + kk];
#pragma unroll
            for (int c = 0; c < 8; c++) bb[c] = Ws[kk * 128 + tx * 8 + c];
#pragma unroll
            for (int r = 0; r < 4; r++)
#pragma unroll
                for (int c = 0; c < 8; c++) acc[r][c] = fmaf(a[r], bb[c], acc[r][c]);
        }
        __syncthreads();
    }
#pragma unroll
    for (int r = 0; r < 4; r++) {
        int gi = i0 + ty * 4 + r;
        float al = alpha[gi];
        float v[8];
        float nrm = 0.f;
        unsigned short hh[8];
#pragma unroll
        for (int c = 0; c < 8; c++) {
            int gc = tx * 8 + c;
            float val = al * (acc[r][c] + bias[gc]) + (1.0f - al) * x[gi * DD + gc];
            v[c] = val;
            nrm = fmaf(val, val, nrm);
            hh[c] = __half_as_ushort(__float2half_rn(val));
        }
        // fp32 sem output (vectorized)
        float4* semv = reinterpret_cast<float4*>(sem + (size_t)gi * DD + tx * 8);
        semv[0] = make_float4(v[0], v[1], v[2], v[3]);
        semv[1] = make_float4(v[4], v[5], v[6], v[7]);
        // fp16 hi image (16B per thread-row)
        int tile = gi >> 7, rr = gi & 127;
        uint4 hp;
        hp.x = (unsigned)hh[0] | ((unsigned)hh[1] << 16);
        hp.y = (unsigned)hh[2] | ((unsigned)hh[3] << 16);
        hp.z = (unsigned)hh[4] | ((unsigned)hh[5] << 16);
        hp.w = (unsigned)hh[6] | ((unsigned)hh[7] << 16);
        *reinterpret_cast<uint4*>(g_semhi + (size_t)tile * TILE_B + (size_t)rr * TSTRIDE + tx * 16) = hp;
        // row norm: reduce over the 16 tx lanes (same half-warp)
#pragma unroll
        for (int o = 1; o <= 8; o <<= 1) nrm += __shfl_xor_sync(0xFFFFFFFFu, nrm, o);
        if (tx == 0) g_semnorm[gi] = nrm;
    }
}

// ---------------------------------------------------------------------------
// fp32 x rows -> fp16 padded tile image + sq norms. One warp per row.
__global__ __launch_bounds__(256) void convert_kernel(const float* __restrict__ x)
{
    int row = blockIdx.x * 8 + (threadIdx.x >> 5);
    int lid = threadIdx.x & 31;

    float4 v = reinterpret_cast<const float4*>(x + (size_t)row * DD)[lid];
    float s = v.x * v.x + v.y * v.y + v.z * v.z + v.w * v.w;
#pragma unroll
    for (int o = 16; o > 0; o >>= 1) s += __shfl_xor_sync(0xFFFFFFFFu, s, o);

    float f[4] = {v.x, v.y, v.z, v.w};
    unsigned short h[4];
#pragma unroll
    for (int q = 0; q < 4; q++) h[q] = __half_as_ushort(__float2half_rn(f[q]));
    unsigned long long hp = (unsigned long long)h[0] | ((unsigned long long)h[1] << 16) |
                            ((unsigned long long)h[2] << 32) | ((unsigned long long)h[3] << 48);

    int tile = row >> 7, rr = row & 127;
    size_t off = (size_t)tile * TILE_B + (size_t)rr * TSTRIDE + lid * 8;
    *reinterpret_cast<unsigned long long*>(g_xhi + off) = hp;

    if (lid == 0) g_xnorm[row] = s;
}

// ---------------------------------------------------------------------------
// Fused fp16 mma.sync pairwise GEMM (1-pass) + batch-hard reduction.
// grid (NJG=32, NTILE=64), 256 threads, warp grid 4x2 (32x64 tile), 2 CTAs/SM.
#define SM_A 0
#define SM_B(buf) (TILE_B + (buf) * TILE_B)
#define SM_CTRL (3 * TILE_B)
#define SM_MBLD(s) (SM_CTRL + (s) * 8)
#define SM_JINFO (SM_CTRL + 16)
#define SM_TOTAL (SM_CTRL + 16 + 1024)

__global__ void __launch_bounds__(256, 2) dist_kernel(const int* __restrict__ label)
{
    extern __shared__ char smem[];
    const uint32_t sb = smem_u32(smem);
    const int t = threadIdx.x;
    const int lane = t & 31, wid = t >> 5;
    const int wm = wid & 3, wn = wid >> 2;      // warp tile (wm*32 rows, wn*64 cols)
    const int itile = blockIdx.y, jg = blockIdx.x;

    if (t == 0) {
        MBAR_INIT(sb + SM_MBLD(0), 1);
        MBAR_INIT(sb + SM_MBLD(1), 1);
    }
    __syncthreads();

    if (t == 0) {
        MBAR_EXPECT(sb + SM_MBLD(0), 2u * TILE_B);
        bulk_g2s(sb + SM_A, gaddr(g_semhi + (size_t)itile * TILE_B), TILE_B, sb + SM_MBLD(0));
        bulk_g2s(sb + SM_B(0), gaddr(g_xhi + (size_t)(jg * JPC) * TILE_B), TILE_B, sb + SM_MBLD(0));
    }

    // per-thread identity: 4 distinct rows (mt 0/1 x row-half 0/1)
    const int q = lane & 3, rquad = lane >> 2;
    int gi4[4];
    int li[4];
#pragma unroll
    for (int s = 0; s < 4; s++) {
        gi4[s] = itile * 128 + wm * 32 + (s >> 1) * 16 + (s & 1) * 8 + rquad;
        li[s] = label[gi4[s]];
    }
    float mpos[4], msame[4], mdiff[4];
#pragma unroll
    for (int s = 0; s < 4; s++) { mpos[s] = -3.0e38f; msame[s] = 3.0e38f; mdiff[s] = 3.0e38f; }

    // ldmatrix base addresses
    const int lr = lane & 7, grp = lane >> 3;
    const uint32_t aOff0 = (uint32_t)(wm * 32 + (grp & 1) * 8 + lr) * TSTRIDE + (grp >> 1) * 16;
    const uint32_t pA0 = sb + SM_A + aOff0;
    const uint32_t pA1 = pA0 + 16u * TSTRIDE;
    const uint32_t bOff = (uint32_t)(wn * 64 + ((grp >> 1) & 1) * 8 + lr) * TSTRIDE + (grp & 1) * 16;

    uint2* jinfo = (uint2*)(smem + SM_JINFO);
    const uint4* jinfo4 = (const uint4*)(smem + SM_JINFO);

    for (int j = 0; j < JPC; j++) {
        const int jt = jg * JPC + j;
        const int buf = j & 1;

        mbar_wait(sb + SM_MBLD(buf), (unsigned)((j >> 1) & 1));
        if (t < 128) {
            uint2 ji;
            ji.x = __float_as_uint(g_xnorm[jt * 128 + t]);
            ji.y = (unsigned)label[jt * 128 + t];
            jinfo[t] = ji;
        }
        __syncthreads();  // jinfo visible; all warps done with previous mainloop -> nb free

        if (t == 0 && j + 1 < JPC) {
            int nb = (j + 1) & 1;
            MBAR_EXPECT(sb + SM_MBLD(nb), (unsigned)TILE_B);
            bulk_g2s(sb + SM_B(nb), gaddr(g_xhi + (size_t)(jt + 1) * TILE_B), TILE_B, sb + SM_MBLD(nb));
        }

        // ---- mainloop: acc = A*B over K=128 (1-pass fp16) ----
        float acc[2][8][4];
#pragma unroll
        for (int mt = 0; mt < 2; mt++)
#pragma unroll
            for (int nt = 0; nt < 8; nt++)
#pragma unroll
                for (int e = 0; e < 4; e++) acc[mt][nt][e] = 0.f;

        const uint32_t pB = sb + SM_B(buf) + bOff;
#pragma unroll
        for (int ks = 0; ks < 8; ks++) {
            unsigned ah[2][4], bh[4][4];
            ldm_x4(ah[0], pA0 + ks * 32);
            ldm_x4(ah[1], pA1 + ks * 32);
#pragma unroll
            for (int np = 0; np < 4; np++)
                ldm_x4(bh[np], pB + np * (16 * TSTRIDE) + ks * 32);
#pragma unroll
            for (int np = 0; np < 4; np++)
#pragma unroll
                for (int mt = 0; mt < 2; mt++) {
                    mma_f16(acc[mt][2 * np],     ah[mt], bh[np]);
                    mma_f16(acc[mt][2 * np + 1], ah[mt], bh[np] + 2);
                }
        }

        // ---- epilogue: u = xn[j] - 2*dot, masked max/min into registers ----
#pragma unroll
        for (int nt = 0; nt < 8; nt++) {
            uint4 v = jinfo4[wn * 32 + nt * 4 + q];    // (xn[jc],lab[jc],xn[jc+1],lab[jc+1])
            float xn0 = __uint_as_float(v.x), xn1 = __uint_as_float(v.z);
            int lb0 = (int)v.y, lb1 = (int)v.w;
            int gj0 = jt * 128 + wn * 64 + nt * 8 + q * 2;
#pragma unroll
            for (int mt = 0; mt < 2; mt++) {
                const float* a4 = acc[mt][nt];
                int s0 = mt * 2, s1 = mt * 2 + 1;
                float u;
                u = fmaf(-2.f, a4[0], xn0);
                if (lb0 == li[s0]) { msame[s0] = fminf(msame[s0], u); if (gi4[s0] != gj0) mpos[s0] = fmaxf(mpos[s0], u); }
                else mdiff[s0] = fminf(mdiff[s0], u);
                u = fmaf(-2.f, a4[1], xn1);
                if (lb1 == li[s0]) { msame[s0] = fminf(msame[s0], u); if (gi4[s0] != gj0 + 1) mpos[s0] = fmaxf(mpos[s0], u); }
                else mdiff[s0] = fminf(mdiff[s0], u);
                u = fmaf(-2.f, a4[2], xn0);
                if (lb0 == li[s1]) { msame[s1] = fminf(msame[s1], u); if (gi4[s1] != gj0) mpos[s1] = fmaxf(mpos[s1], u); }
                else mdiff[s1] = fminf(mdiff[s1], u);
                u = fmaf(-2.f, a4[3], xn1);
                if (lb1 == li[s1]) { msame[s1] = fminf(msame[s1], u); if (gi4[s1] != gj0 + 1) mpos[s1] = fmaxf(mpos[s1], u); }
                else mdiff[s1] = fminf(mdiff[s1], u);
            }
        }
        __syncthreads();   // epilogue done before next iter rewrites jinfo
    }

    // quad reduction (4 lanes share the same rows), then one atomic triple per row
#pragma unroll
    for (int s = 0; s < 4; s++) {
#pragma unroll
        for (int o = 1; o <= 2; o <<= 1) {
            mpos[s] = fmaxf(mpos[s], __shfl_xor_sync(0xFFFFFFFFu, mpos[s], o));
            msame[s] = fminf(msame[s], __shfl_xor_sync(0xFFFFFFFFu, msame[s], o));
            mdiff[s] = fminf(mdiff[s], __shfl_xor_sync(0xFFFFFFFFu, mdiff[s], o));
        }
        if (q == 0) {
            if (mpos[s] > -2.9e38f) atomicMax(&g_mp[gi4[s]], fmap(mpos[s]));
            atomicMin(&g_md[gi4[s]], fmap(mdiff[s]));
            atomicMin(&g_ms[gi4[s]], fmap(msame[s]));
        }
    }
}

// ---------------------------------------------------------------------------
__global__ void final_kernel(float* __restrict__ out) {
    int i = blockIdx.x * blockDim.x + threadIdx.x;
    if (i >= NN) return;
    const float DEPS = (float)DD * 1e-16f;
    float sn = g_semnorm[i];
    unsigned mp = g_mp[i], md = g_md[i], ms = g_ms[i];
    float fp = (mp == 0u) ? 0.f : sqrtf(fmaxf(sn + funmap(mp), 0.f) + DEPS);
    float d1 = (md == 0xFFFFFFFFu) ? 3.0e38f : sqrtf(fmaxf(sn + funmap(md), 0.f) + DEPS);
    float d2 = (ms == 0xFFFFFFFFu) ? 3.0e38f : sqrtf(fmaxf(sn + funmap(ms), 0.f) + DEPS) + 1e8f;
    float cn = fminf(d1, d2);
    float z = fp - cn;
    out[i] = fmaxf(z, 0.f) + log1pf(expf(-fabsf(z)));
}

// ---------------------------------------------------------------------------
extern "C" void kernel_launch(void* const* d_in, const int* in_sizes, int n_in,
                              void* d_out, int out_size)
{
    const float* x = (const float*)d_in[0];
    const float* wv = (const float*)d_in[1];
    const int* label = (const int*)d_in[2];
    const float* alpha = (const float*)d_in[3];
    const float* Wm = (const float*)d_in[4];
    const float* bias = (const float*)d_in[5];

    float* out = (float*)d_out;       // [N] diff, then [N,D] sem
    float* sem = out + NN;

    cudaFuncSetAttribute(dist_kernel, cudaFuncAttributeMaxDynamicSharedMemorySize, SM_TOTAL);

    sem_kernel<<<NN / 64, 256>>>(wv, Wm, bias, x, alpha, sem);
    convert_kernel<<<NN / 8, 256>>>(x);
    dim3 grid(NJG, NTILE);
    dist_kernel<<<grid, 256, SM_TOTAL>>>(label);
    final_kernel<<<(NN + 255) / 256, 256>>>(out);
}